// round 11
// baseline (speedup 1.0000x reference)
#include <cuda_runtime.h>
#include <cstdint>

#define NBINS     8192        // raw top-13 bits of float bits
#define BIN_SHIFT 19
#define SUB_SHIFT 7           // next 12 bits for tie-bin refinement
#define CAND_MAX  4096
#define SORT_N    4096
#define NT        1024
#define NGROUPS   128         // 8192 / 64
#define GRP       64

typedef unsigned long long ull;

// Monotone transform (finite floats): u(a) > u(b) <=> a > b.
__device__ __forceinline__ uint32_t key_of(float v) {
    uint32_t b = __float_as_uint(v);
    return (b & 0x80000000u) ? ~b : (b | 0x80000000u);
}
// Descending-value position -> raw bin index.
__device__ __forceinline__ int bin_of_pos(int p) {
    return (p < 4096) ? (0x0FFF - p) : p;
}

__global__ __launch_bounds__(NT, 1)
void topk_kernel(const float* __restrict__ scores,
                 const int*   __restrict__ bndA,
                 const int*   __restrict__ bndB,
                 float*       __restrict__ out,   // output dtype = float32
                 int S, int K) {
    __shared__ union {
        uint32_t hist[NBINS];    // 32 KB (histogram / sub-histogram)
        ull      cand[SORT_N];   // 32 KB (gather + bitonic sort)
    } sh;
    __shared__ uint32_t gsum[NGROUPS];
    __shared__ float s_thr;
    __shared__ int s_n, s_bb, s_neg, s_before, s_refine, s_T;

    const int row = blockIdx.x, tid = threadIdx.x;
    const int a = bndA[row], b = bndB[row];
    int start = max(0, min(min(a, b), S));
    int end   = max(start, min(max(a, b), S));
    const int W = end - start;
    const float* rowp = scores + (size_t)row * S;
    float* orow = out + (size_t)row * K;

    if (W <= 0) { for (int k = tid; k < K; k += NT) orow[k] = (float)k; return; }

    int vstart = (start + 3) & ~3; if (vstart > end) vstart = end;
    int vend   = end & ~3;         if (vend < vstart) vend = vstart;
    const float4* vp = reinterpret_cast<const float4*>(rowp);
    const int vlo = vstart >> 2, vhi = vend >> 2;
    const int n4 = vhi - vlo;

    // mode 0 = sampled histogram, 1 = exact histogram (fallback), 2 = take-all
    int mode = (W > CAND_MAX) ? 0 : 2;
    float thr;
    int n;

    for (;;) {
        if (mode == 2) {
            thr = -3.4028235e38f;
        } else {
            // ---- zero histogram ----
            for (int i = tid; i < NBINS; i += NT) sh.hist[i] = 0;
            __syncthreads();

            // ---- histogram raw top-13 bits ----
            if (mode == 0) {
                // 1/8 of float4s: consecutive tids hit distinct 128B lines
                for (int it = tid; it * 8 < n4; it += NT) {
                    float4 v = vp[vlo + it * 8];
                    atomicAdd(&sh.hist[__float_as_uint(v.x) >> BIN_SHIFT], 1u);
                    atomicAdd(&sh.hist[__float_as_uint(v.y) >> BIN_SHIFT], 1u);
                    atomicAdd(&sh.hist[__float_as_uint(v.z) >> BIN_SHIFT], 1u);
                    atomicAdd(&sh.hist[__float_as_uint(v.w) >> BIN_SHIFT], 1u);
                }
            } else {
                for (int i = start + tid; i < vstart; i += NT)
                    atomicAdd(&sh.hist[__float_as_uint(rowp[i]) >> BIN_SHIFT], 1u);
                for (int i = vend + tid; i < end; i += NT)
                    atomicAdd(&sh.hist[__float_as_uint(rowp[i]) >> BIN_SHIFT], 1u);
                for (int i = vlo + tid; i < vhi; i += NT) {
                    float4 v = vp[i];
                    atomicAdd(&sh.hist[__float_as_uint(v.x) >> BIN_SHIFT], 1u);
                    atomicAdd(&sh.hist[__float_as_uint(v.y) >> BIN_SHIFT], 1u);
                    atomicAdd(&sh.hist[__float_as_uint(v.z) >> BIN_SHIFT], 1u);
                    atomicAdd(&sh.hist[__float_as_uint(v.w) >> BIN_SHIFT], 1u);
                }
            }
            __syncthreads();

            // ---- group sums over descending-value positions ----
            {
                int warp = tid >> 5, lane = tid & 31;
                for (int g = warp; g < NGROUPS; g += NT / 32) {
                    uint32_t s = 0;
                    #pragma unroll
                    for (int j = 0; j < GRP / 32; ++j)
                        s += sh.hist[bin_of_pos(g * GRP + j * 32 + lane)];
                    #pragma unroll
                    for (int o = 16; o > 0; o >>= 1)
                        s += __shfl_down_sync(0xffffffffu, s, o);
                    if (lane == 0) gsum[g] = s;
                }
            }
            __syncthreads();

            // ---- thread 0: pick tie bin for target T ----
            if (tid == 0) {
                int T;
                if (mode == 0) {
                    int ns = 4 * ((n4 + 7) / 8);     // sampled element count
                    long long tt = ((long long)((K + CAND_MAX) / 2) * ns) / W;
                    T = (tt < 1) ? 1 : (int)tt;
                } else {
                    T = K;
                }
                s_T = T;
                uint32_t acc = 0;
                int g = 0;
                for (; g < NGROUPS; ++g) {
                    if (acc + gsum[g] >= (uint32_t)T) break;
                    acc += gsum[g];
                }
                if (g == NGROUPS) {          // defensive; shouldn't happen
                    s_thr = -3.4028235e38f;
                    s_refine = 0;
                } else {
                    int pp = g * GRP;
                    for (int t = 0; t < GRP; ++t) {
                        int p = g * GRP + t;
                        uint32_t h = sh.hist[bin_of_pos(p)];
                        if (acc + h >= (uint32_t)T) { pp = p; break; }
                        acc += h;
                    }
                    int bin = bin_of_pos(pp);
                    bool neg = (pp >= 4096);
                    uint32_t h = sh.hist[bin];
                    // sampled: always refine (bin granularity too coarse);
                    // exact: refine only if whole tie bin would overflow.
                    bool refine = (mode == 0) || (acc + h > (uint32_t)CAND_MAX);
                    if (!refine) {
                        uint32_t tb = ((uint32_t)bin << BIN_SHIFT) |
                                      (neg ? ((1u << BIN_SHIFT) - 1u) : 0u);
                        s_thr = __uint_as_float(tb);
                        s_refine = 0;
                    } else {
                        s_bb = bin; s_neg = neg; s_before = (int)acc;
                        s_refine = 1;
                    }
                }
            }
            __syncthreads();

            // ---- refinement: 12 more bits inside the tie bin ----
            if (s_refine) {
                const uint32_t bb = (uint32_t)s_bb;
                for (int i = tid; i < 4096; i += NT) sh.hist[i] = 0;
                __syncthreads();
                if (mode == 0) {
                    for (int it = tid; it * 8 < n4; it += NT) {
                        float4 v = vp[vlo + it * 8];
                        uint32_t bx;
                        bx = __float_as_uint(v.x);
                        if ((bx >> BIN_SHIFT) == bb) atomicAdd(&sh.hist[(bx >> SUB_SHIFT) & 0xFFFu], 1u);
                        bx = __float_as_uint(v.y);
                        if ((bx >> BIN_SHIFT) == bb) atomicAdd(&sh.hist[(bx >> SUB_SHIFT) & 0xFFFu], 1u);
                        bx = __float_as_uint(v.z);
                        if ((bx >> BIN_SHIFT) == bb) atomicAdd(&sh.hist[(bx >> SUB_SHIFT) & 0xFFFu], 1u);
                        bx = __float_as_uint(v.w);
                        if ((bx >> BIN_SHIFT) == bb) atomicAdd(&sh.hist[(bx >> SUB_SHIFT) & 0xFFFu], 1u);
                    }
                } else {
                    for (int i = start + tid; i < end; i += NT) {
                        uint32_t bx = __float_as_uint(rowp[i]);
                        if ((bx >> BIN_SHIFT) == bb)
                            atomicAdd(&sh.hist[(bx >> SUB_SHIFT) & 0xFFFu], 1u);
                    }
                }
                __syncthreads();
                if (tid == 0) {
                    uint32_t need = (uint32_t)(s_T - s_before);
                    uint32_t acc = 0, tb;
                    uint32_t bb2 = (uint32_t)s_bb;
                    if (!s_neg) {           // positive: value desc == sub desc
                        int ss = 0;
                        for (int i = 4095; i >= 0; --i) {
                            if (acc + sh.hist[i] >= need) { ss = i; break; }
                            acc += sh.hist[i];
                        }
                        tb = (bb2 << BIN_SHIFT) | ((uint32_t)ss << SUB_SHIFT);
                    } else {                // negative: value desc == sub asc
                        int ss = 4095;
                        for (int i = 0; i < 4096; ++i) {
                            if (acc + sh.hist[i] >= need) { ss = i; break; }
                            acc += sh.hist[i];
                        }
                        tb = (bb2 << BIN_SHIFT) | ((uint32_t)ss << SUB_SHIFT) |
                             ((1u << SUB_SHIFT) - 1u);
                    }
                    s_thr = __uint_as_float(tb);
                }
                __syncthreads();
            }
            thr = s_thr;
        }

        // ---- gather: zero pad buffer, then one float compare per element ----
        __syncthreads();
        for (int i = tid; i < SORT_N; i += NT) sh.cand[i] = 0ull;
        if (tid == 0) s_n = 0;
        __syncthreads();

        for (int i = start + tid; i < vstart; i += NT) {
            float v = rowp[i];
            if (v >= thr) {
                int p = atomicAdd(&s_n, 1);
                if (p < CAND_MAX) sh.cand[p] = ((ull)key_of(v) << 32) | (uint32_t)(~i);
            }
        }
        for (int i = vend + tid; i < end; i += NT) {
            float v = rowp[i];
            if (v >= thr) {
                int p = atomicAdd(&s_n, 1);
                if (p < CAND_MAX) sh.cand[p] = ((ull)key_of(v) << 32) | (uint32_t)(~i);
            }
        }
        for (int i = vlo + tid; i < vhi; i += NT) {
            float4 v = vp[i];
            float mx = fmaxf(fmaxf(v.x, v.y), fmaxf(v.z, v.w));
            if (mx >= thr) {
                int base = i << 2;
                if (v.x >= thr) {
                    int p = atomicAdd(&s_n, 1);
                    if (p < CAND_MAX) sh.cand[p] = ((ull)key_of(v.x) << 32) | (uint32_t)(~(base + 0));
                }
                if (v.y >= thr) {
                    int p = atomicAdd(&s_n, 1);
                    if (p < CAND_MAX) sh.cand[p] = ((ull)key_of(v.y) << 32) | (uint32_t)(~(base + 1));
                }
                if (v.z >= thr) {
                    int p = atomicAdd(&s_n, 1);
                    if (p < CAND_MAX) sh.cand[p] = ((ull)key_of(v.z) << 32) | (uint32_t)(~(base + 2));
                }
                if (v.w >= thr) {
                    int p = atomicAdd(&s_n, 1);
                    if (p < CAND_MAX) sh.cand[p] = ((ull)key_of(v.w) << 32) | (uint32_t)(~(base + 3));
                }
            }
        }
        __syncthreads();
        n = s_n;
        if (mode == 0 && (n < K || n > CAND_MAX)) {   // sampled miss: exact redo
            mode = 1;
            __syncthreads();
            continue;
        }
        n = min(n, CAND_MAX);
        break;
    }

    // ---- bitonic sort 4096 u64 descending: smem only for j>=128,
    //      shfl for j=4..64, registers for j=1,2. 4 elements/thread. ----
    {
        ull x[4];
        #pragma unroll
        for (int m = 0; m < 4; ++m) x[m] = sh.cand[4 * tid + m];

        for (int k = 2; k <= SORT_N; k <<= 1) {
            if (k > 128) {
                #pragma unroll
                for (int m = 0; m < 4; ++m) sh.cand[4 * tid + m] = x[m];
                __syncthreads();
                for (int j = k >> 1; j >= 128; j >>= 1) {
                    #pragma unroll
                    for (int m = 0; m < 4; ++m) {
                        int i = tid + m * NT;
                        int p = i ^ j;
                        if (p > i) {
                            ull xa = sh.cand[i], xb = sh.cand[p];
                            bool desc = (i & k) == 0;
                            if (desc ? (xa < xb) : (xa > xb)) {
                                sh.cand[i] = xb; sh.cand[p] = xa;
                            }
                        }
                    }
                    __syncthreads();
                }
                #pragma unroll
                for (int m = 0; m < 4; ++m) x[m] = sh.cand[4 * tid + m];
            }
            // warp substages: j = min(k/2,64) .. 4  (partner lane = lane ^ (j/4))
            for (int j = min(k >> 1, 64); j >= 4; j >>= 1) {
                int l = j >> 2;
                #pragma unroll
                for (int m = 0; m < 4; ++m) {
                    ull y = __shfl_xor_sync(0xffffffffu, x[m], l);
                    int i = 4 * tid + m;
                    bool desc  = (i & k) == 0;
                    bool lower = (i & j) == 0;
                    bool takeMax = (desc == lower);
                    x[m] = takeMax ? (x[m] > y ? x[m] : y) : (x[m] < y ? x[m] : y);
                }
            }
            if (k >= 4) {   // j = 2: pairs (0,2),(1,3)
                #pragma unroll
                for (int m = 0; m < 2; ++m) {
                    int i = 4 * tid + m;
                    bool desc = (i & k) == 0;
                    ull xa = x[m], xb = x[m + 2];
                    if (desc ? (xa < xb) : (xa > xb)) { x[m] = xb; x[m + 2] = xa; }
                }
            }
            {               // j = 1: pairs (0,1),(2,3)
                #pragma unroll
                for (int m = 0; m < 4; m += 2) {
                    int i = 4 * tid + m;
                    bool desc = (i & k) == 0;
                    ull xa = x[m], xb = x[m + 1];
                    if (desc ? (xa < xb) : (xa > xb)) { x[m] = xb; x[m + 1] = xa; }
                }
            }
        }
        #pragma unroll
        for (int m = 0; m < 4; ++m) sh.cand[4 * tid + m] = x[m];
        __syncthreads();
    }

    // ---- emit top-K indices as float values ----
    for (int k = tid; k < K; k += NT)
        orow[k] = (k < n) ? (float)(int)(~(uint32_t)sh.cand[k]) : (float)k;
}

extern "C" void kernel_launch(void* const* d_in, const int* in_sizes, int n_in,
                              void* d_out, int out_size) {
    int big = 0;
    for (int i = 1; i < n_in; ++i)
        if (in_sizes[i] > in_sizes[big]) big = i;
    int s0 = -1, s1 = -1;
    for (int i = 0; i < n_in; ++i) {
        if (i == big) continue;
        if (s0 < 0) s0 = i; else if (s1 < 0) s1 = i;
    }

    const int B = in_sizes[s0];
    const int S = in_sizes[big] / (B > 0 ? B : 1);
    const int K = out_size / (B > 0 ? B : 1);

    const float* scores = (const float*)d_in[big];
    const int*   bA     = (const int*)d_in[s0];
    const int*   bB     = (const int*)d_in[s1];
    float*       outp   = (float*)d_out;

    topk_kernel<<<B, NT>>>(scores, bA, bB, outp, S, K);
}

// round 12
// speedup vs baseline: 1.8479x; 1.8479x over previous
#include <cuda_runtime.h>
#include <cstdint>

#define NBINS     8192        // raw top-13 bits of float bits
#define BIN_SHIFT 19
#define NSUB      256         // 8-bit refinement inside the tie bin
#define SUB_SHIFT (BIN_SHIFT - 8)
#define SUB_MASK  0xFFu
#define CAND_MAX  4096
#define SORT_N    4096
#define NT        1024
#define NGROUPS   128         // 8192 / 64
#define GRP       64

typedef unsigned long long ull;

// Monotone transform (finite floats): u(a) > u(b) <=> a > b.
__device__ __forceinline__ uint32_t key_of(float v) {
    uint32_t b = __float_as_uint(v);
    return (b & 0x80000000u) ? ~b : (b | 0x80000000u);
}
// Descending-value position -> raw bin index.
__device__ __forceinline__ int bin_of_pos(int p) {
    return (p < 4096) ? (0x0FFF - p) : p;
}

__global__ __launch_bounds__(NT, 1)
void topk_kernel(const float* __restrict__ scores,
                 const int*   __restrict__ bndA,
                 const int*   __restrict__ bndB,
                 float*       __restrict__ out,   // output dtype = float32
                 int S, int K) {
    __shared__ union {
        uint32_t hist[NBINS];    // 32 KB (histogram; refine reuses first NSUB)
        ull      cand[SORT_N];   // 32 KB (gather + bitonic sort)
    } sh;
    __shared__ uint32_t gsum[NGROUPS];
    __shared__ float s_thr;
    __shared__ int s_n, s_bb, s_neg, s_before, s_refine, s_T;

    const int row = blockIdx.x, tid = threadIdx.x;
    const int a = bndA[row], b = bndB[row];
    int start = max(0, min(min(a, b), S));
    int end   = max(start, min(max(a, b), S));
    const int W = end - start;
    const float* rowp = scores + (size_t)row * S;
    float* orow = out + (size_t)row * K;

    if (W <= 0) { for (int k = tid; k < K; k += NT) orow[k] = (float)k; return; }

    int vstart = (start + 3) & ~3; if (vstart > end) vstart = end;
    int vend   = end & ~3;         if (vend < vstart) vend = vstart;
    const float4* vp = reinterpret_cast<const float4*>(rowp);
    const int vlo = vstart >> 2, vhi = vend >> 2;
    const int n4 = vhi - vlo;

    // mode 0 = sampled histogram, 1 = exact histogram (fallback), 2 = take-all
    int mode = (W > CAND_MAX) ? 0 : 2;
    float thr;
    int n;

    for (;;) {
        if (mode == 2) {
            thr = -3.4028235e38f;
        } else {
            for (int i = tid; i < NBINS; i += NT) sh.hist[i] = 0;
            __syncthreads();

            // ---- pass 1: histogram raw top-13 bits ----
            if (mode == 0) {
                for (int it = tid; it * 8 < n4; it += NT) {
                    float4 v = vp[vlo + it * 8];
                    atomicAdd(&sh.hist[__float_as_uint(v.x) >> BIN_SHIFT], 1u);
                    atomicAdd(&sh.hist[__float_as_uint(v.y) >> BIN_SHIFT], 1u);
                    atomicAdd(&sh.hist[__float_as_uint(v.z) >> BIN_SHIFT], 1u);
                    atomicAdd(&sh.hist[__float_as_uint(v.w) >> BIN_SHIFT], 1u);
                }
            } else {
                for (int i = start + tid; i < vstart; i += NT)
                    atomicAdd(&sh.hist[__float_as_uint(rowp[i]) >> BIN_SHIFT], 1u);
                for (int i = vend + tid; i < end; i += NT)
                    atomicAdd(&sh.hist[__float_as_uint(rowp[i]) >> BIN_SHIFT], 1u);
                for (int i = vlo + tid; i < vhi; i += NT) {
                    float4 v = vp[i];
                    atomicAdd(&sh.hist[__float_as_uint(v.x) >> BIN_SHIFT], 1u);
                    atomicAdd(&sh.hist[__float_as_uint(v.y) >> BIN_SHIFT], 1u);
                    atomicAdd(&sh.hist[__float_as_uint(v.z) >> BIN_SHIFT], 1u);
                    atomicAdd(&sh.hist[__float_as_uint(v.w) >> BIN_SHIFT], 1u);
                }
            }
            __syncthreads();

            // ---- group sums over descending-value positions ----
            {
                int warp = tid >> 5, lane = tid & 31;
                for (int g = warp; g < NGROUPS; g += NT / 32) {
                    uint32_t s = 0;
                    #pragma unroll
                    for (int j = 0; j < GRP / 32; ++j)
                        s += sh.hist[bin_of_pos(g * GRP + j * 32 + lane)];
                    #pragma unroll
                    for (int o = 16; o > 0; o >>= 1)
                        s += __shfl_down_sync(0xffffffffu, s, o);
                    if (lane == 0) gsum[g] = s;
                }
            }
            __syncthreads();

            // ---- thread 0: pick tie bin for target T ----
            if (tid == 0) {
                int T;
                if (mode == 0) {
                    int ns = 4 * ((n4 + 7) / 8);     // sampled element count
                    long long tt = ((long long)((K + CAND_MAX) / 2) * ns) / W;
                    T = (tt < 1) ? 1 : (int)tt;
                } else {
                    T = K;
                }
                s_T = T;
                uint32_t acc = 0;
                int g = 0;
                for (; g < NGROUPS; ++g) {
                    if (acc + gsum[g] >= (uint32_t)T) break;
                    acc += gsum[g];
                }
                if (g == NGROUPS) {
                    s_thr = -3.4028235e38f;
                    s_refine = 0;
                } else {
                    int pp = g * GRP;
                    for (int t = 0; t < GRP; ++t) {
                        int p = g * GRP + t;
                        uint32_t h = sh.hist[bin_of_pos(p)];
                        if (acc + h >= (uint32_t)T) { pp = p; break; }
                        acc += h;
                    }
                    int bin = bin_of_pos(pp);
                    bool neg = (pp >= 4096);
                    uint32_t h = sh.hist[bin];
                    bool refine = (mode == 0) || (acc + h > (uint32_t)CAND_MAX);
                    if (!refine) {
                        uint32_t tb = ((uint32_t)bin << BIN_SHIFT) |
                                      (neg ? ((1u << BIN_SHIFT) - 1u) : 0u);
                        s_thr = __uint_as_float(tb);
                        s_refine = 0;
                    } else {
                        s_bb = bin; s_neg = neg; s_before = (int)acc;
                        s_refine = 1;
                    }
                }
            }
            __syncthreads();

            // ---- refinement: 8 more bits inside the tie bin (256 sub-bins) ----
            if (s_refine) {
                const uint32_t bb = (uint32_t)s_bb;
                for (int i = tid; i < NSUB; i += NT) sh.hist[i] = 0;
                __syncthreads();
                if (mode == 0) {
                    for (int it = tid; it * 8 < n4; it += NT) {
                        float4 v = vp[vlo + it * 8];
                        uint32_t bx;
                        bx = __float_as_uint(v.x);
                        if ((bx >> BIN_SHIFT) == bb) atomicAdd(&sh.hist[(bx >> SUB_SHIFT) & SUB_MASK], 1u);
                        bx = __float_as_uint(v.y);
                        if ((bx >> BIN_SHIFT) == bb) atomicAdd(&sh.hist[(bx >> SUB_SHIFT) & SUB_MASK], 1u);
                        bx = __float_as_uint(v.z);
                        if ((bx >> BIN_SHIFT) == bb) atomicAdd(&sh.hist[(bx >> SUB_SHIFT) & SUB_MASK], 1u);
                        bx = __float_as_uint(v.w);
                        if ((bx >> BIN_SHIFT) == bb) atomicAdd(&sh.hist[(bx >> SUB_SHIFT) & SUB_MASK], 1u);
                    }
                } else {
                    for (int i = start + tid; i < end; i += NT) {
                        uint32_t bx = __float_as_uint(rowp[i]);
                        if ((bx >> BIN_SHIFT) == bb)
                            atomicAdd(&sh.hist[(bx >> SUB_SHIFT) & SUB_MASK], 1u);
                    }
                }
                __syncthreads();
                if (tid == 0) {
                    uint32_t need = (uint32_t)(s_T - s_before);
                    uint32_t acc = 0, tb;
                    uint32_t bb2 = (uint32_t)s_bb;
                    if (!s_neg) {           // positive: value desc == sub desc
                        int ss = 0;
                        for (int i = NSUB - 1; i >= 0; --i) {
                            if (acc + sh.hist[i] >= need) { ss = i; break; }
                            acc += sh.hist[i];
                        }
                        tb = (bb2 << BIN_SHIFT) | ((uint32_t)ss << SUB_SHIFT);
                    } else {                // negative: value desc == sub asc
                        int ss = NSUB - 1;
                        for (int i = 0; i < NSUB; ++i) {
                            if (acc + sh.hist[i] >= need) { ss = i; break; }
                            acc += sh.hist[i];
                        }
                        tb = (bb2 << BIN_SHIFT) | ((uint32_t)ss << SUB_SHIFT) |
                             ((1u << SUB_SHIFT) - 1u);
                    }
                    s_thr = __uint_as_float(tb);
                }
                __syncthreads();
            }
            thr = s_thr;
        }

        // ---- gather: zero pad buffer, then one float compare per element ----
        __syncthreads();
        for (int i = tid; i < SORT_N; i += NT) sh.cand[i] = 0ull;
        if (tid == 0) s_n = 0;
        __syncthreads();

        for (int i = start + tid; i < vstart; i += NT) {
            float v = rowp[i];
            if (v >= thr) {
                int p = atomicAdd(&s_n, 1);
                if (p < CAND_MAX) sh.cand[p] = ((ull)key_of(v) << 32) | (uint32_t)(~i);
            }
        }
        for (int i = vend + tid; i < end; i += NT) {
            float v = rowp[i];
            if (v >= thr) {
                int p = atomicAdd(&s_n, 1);
                if (p < CAND_MAX) sh.cand[p] = ((ull)key_of(v) << 32) | (uint32_t)(~i);
            }
        }
        for (int i = vlo + tid; i < vhi; i += NT) {
            float4 v = vp[i];
            float mx = fmaxf(fmaxf(v.x, v.y), fmaxf(v.z, v.w));
            if (mx >= thr) {
                int base = i << 2;
                if (v.x >= thr) {
                    int p = atomicAdd(&s_n, 1);
                    if (p < CAND_MAX) sh.cand[p] = ((ull)key_of(v.x) << 32) | (uint32_t)(~(base + 0));
                }
                if (v.y >= thr) {
                    int p = atomicAdd(&s_n, 1);
                    if (p < CAND_MAX) sh.cand[p] = ((ull)key_of(v.y) << 32) | (uint32_t)(~(base + 1));
                }
                if (v.z >= thr) {
                    int p = atomicAdd(&s_n, 1);
                    if (p < CAND_MAX) sh.cand[p] = ((ull)key_of(v.z) << 32) | (uint32_t)(~(base + 2));
                }
                if (v.w >= thr) {
                    int p = atomicAdd(&s_n, 1);
                    if (p < CAND_MAX) sh.cand[p] = ((ull)key_of(v.w) << 32) | (uint32_t)(~(base + 3));
                }
            }
        }
        __syncthreads();
        n = s_n;
        if (mode == 0 && (n < K || n > CAND_MAX)) {   // sampled miss: exact redo
            mode = 1;
            __syncthreads();
            continue;
        }
        n = min(n, CAND_MAX);
        break;
    }

    // ---- bitonic sort 4096 u64, descending (plain smem — R10-proven) ----
    for (int kk = 2; kk <= SORT_N; kk <<= 1) {
        for (int j = kk >> 1; j > 0; j >>= 1) {
            #pragma unroll
            for (int m = 0; m < SORT_N / NT; ++m) {
                int i = tid + m * NT;
                int ixj = i ^ j;
                if (ixj > i) {
                    ull x = sh.cand[i], y = sh.cand[ixj];
                    bool up = ((i & kk) == 0);
                    if (up ? (x < y) : (x > y)) {
                        sh.cand[i] = y;
                        sh.cand[ixj] = x;
                    }
                }
            }
            __syncthreads();
        }
    }

    // ---- emit top-K indices as float values ----
    for (int k = tid; k < K; k += NT)
        orow[k] = (k < n) ? (float)(int)(~(uint32_t)sh.cand[k]) : (float)k;
}

extern "C" void kernel_launch(void* const* d_in, const int* in_sizes, int n_in,
                              void* d_out, int out_size) {
    int big = 0;
    for (int i = 1; i < n_in; ++i)
        if (in_sizes[i] > in_sizes[big]) big = i;
    int s0 = -1, s1 = -1;
    for (int i = 0; i < n_in; ++i) {
        if (i == big) continue;
        if (s0 < 0) s0 = i; else if (s1 < 0) s1 = i;
    }

    const int B = in_sizes[s0];
    const int S = in_sizes[big] / (B > 0 ? B : 1);
    const int K = out_size / (B > 0 ? B : 1);

    const float* scores = (const float*)d_in[big];
    const int*   bA     = (const int*)d_in[s0];
    const int*   bB     = (const int*)d_in[s1];
    float*       outp   = (float*)d_out;

    topk_kernel<<<B, NT>>>(scores, bA, bB, outp, S, K);
}